// round 11
// baseline (speedup 1.0000x reference)
#include <cuda_runtime.h>
#include <cstdint>

// CategorySpecificLinear via mma.sync.m16n8k8 TF32 (base sm_103; tcgen05 is
// rejected by this bench's ptxas target).
//
// Round 11: r9's pipeline schedule (4-stage cp.async, mid-chunk barrier+ISSUE,
// cross-chunk ks0 fragment preload) in r8's ROLLED loop form. The r9/r10 x4
// unroll kept 4 chunk-bodies' pointers live -> 255 regs -> spills (alu 25%).
// One rolled body with dynamic stage index stays within ~210 regs.

#define A_STAGE  32768                 // 256 x 32 f32, 128B rows
#define B_STAGE  17408                 // 32 x 136 f32
#define B_REG    (4 * A_STAGE)         // 131072
#define SMEM_DYN (4 * A_STAGE + 4 * B_STAGE)   // 200704

static __device__ __forceinline__ uint32_t smem_u32(const void* p){
    uint32_t a;
    asm("{ .reg .u64 t; cvta.to.shared.u64 t, %1; cvt.u32.u64 %0, t; }" : "=r"(a) : "l"(p));
    return a;
}
static __device__ __forceinline__ void cp16(uint32_t dst, const void* src){
    asm volatile("cp.async.cg.shared.global [%0], [%1], 16;"
                 :: "r"(dst), "l"(src) : "memory");
}
static __device__ __forceinline__ uint32_t f2tf(uint32_t bits){
    uint32_t r;
    asm("cvt.rna.tf32.f32 %0, %1;" : "=r"(r) : "f"(__uint_as_float(bits)));
    return r;
}
static __device__ __forceinline__ void mma_tf32(float d[4],
                                                uint32_t a0, uint32_t a1,
                                                uint32_t a2, uint32_t a3,
                                                uint32_t b0, uint32_t b1){
    asm volatile(
        "mma.sync.aligned.m16n8k8.row.col.f32.tf32.tf32.f32 "
        "{%0,%1,%2,%3}, {%4,%5,%6,%7}, {%8,%9}, {%0,%1,%2,%3};"
        : "+f"(d[0]), "+f"(d[1]), "+f"(d[2]), "+f"(d[3])
        : "r"(a0), "r"(a1), "r"(a2), "r"(a3), "r"(b0), "r"(b1));
}
static __device__ __forceinline__ uint32_t lds32(const char* p){
    return *(const uint32_t*)p;
}

__global__ __launch_bounds__(256, 1)
void cslin_mma9_kernel(const float* __restrict__ x,
                       const int*   __restrict__ cat_ids,
                       const float* __restrict__ W,
                       const float* __restrict__ bias,
                       float*       __restrict__ y)
{
    constexpr int IDIM = 1024, ODIM = 1024, TDIM = 512;
    extern __shared__ char dsm[];

    const int tid  = threadIdx.x;
    const int wid  = tid >> 5;
    const int lane = tid & 31;
    const int la3  = lane & 3;
    const int lg   = lane >> 2;

    const int n0 = blockIdx.x * 128;
    const int m0 = blockIdx.y * 256;
    const int bb = blockIdx.z;
    const int cat = __ldg(cat_ids + bb);

    const float* xb = x + (size_t)bb  * TDIM * IDIM;
    const float* Wc = W + (size_t)cat * IDIM * ODIM;
    const float* bc = bias + (size_t)cat * ODIM;
    float*       yb = y + (size_t)bb  * TDIM * ODIM;

    // ---- cp.async geometry ----
    const float* aSrc = xb + (size_t)(m0 + (tid >> 3)) * IDIM + ((tid & 7) << 2);
    const uint32_t aDst = smem_u32(dsm)
        + (uint32_t)((tid >> 3) * 128)
        + (uint32_t)((((tid & 7) << 4)) ^ ((((tid >> 3) & 7)) << 4));
    const float* bSrc = Wc + (size_t)(tid >> 5) * ODIM + n0 + ((tid & 31) << 2);
    const uint32_t bDst = smem_u32(dsm) + B_REG
        + (uint32_t)((tid >> 5) * 544 + ((tid & 31) << 4));

#define ISSUE(KC, S)                                                          \
    do {                                                                      \
        const float* _as = aSrc + (KC);                                       \
        const uint32_t _ad = aDst + (uint32_t)((S) * A_STAGE);                \
        _Pragma("unroll")                                                     \
        for (int i = 0; i < 8; i++)                                           \
            cp16(_ad + (uint32_t)(i * 4096), _as + (size_t)(32 * i) * IDIM);  \
        const float* _bs = bSrc + (size_t)(KC) * ODIM;                        \
        const uint32_t _bd = bDst + (uint32_t)((S) * B_STAGE);                \
        _Pragma("unroll")                                                     \
        for (int i = 0; i < 4; i++)                                           \
            cp16(_bd + (uint32_t)(i * 4352), _bs + (size_t)(8 * i) * ODIM);   \
    } while (0)

    // ---- warp tile 64x64 invariants ----
    const int wm = (wid & 3) * 64;
    const int wn = (wid >> 2) * 64;

    const uint32_t swzA = (uint32_t)(lg << 4);
    const uint32_t aInv = (uint32_t)((wm + lg) * 128);
    const uint32_t bInv = (uint32_t)(la3 * 544 + (wn + lg) * 4);
    const uint32_t aK   = (uint32_t)(la3 * 4);

    float acc[4][8][4];
    #pragma unroll
    for (int i = 0; i < 4; i++)
        #pragma unroll
        for (int j = 0; j < 8; j++)
            #pragma unroll
            for (int q = 0; q < 4; q++) acc[i][j][q] = 0.f;

    uint32_t fa0[16], fb0[16], fa1[16], fb1[16];

#define LOAD_FRAGS(FA, FB, SA, SB, KS)                                        \
    do {                                                                      \
        const char* _pb = (SB) + (bInv + (KS) * 4352);                        \
        _Pragma("unroll")                                                     \
        for (int j = 0; j < 8; j++){                                          \
            FB[2*j]   = f2tf(lds32(_pb + j * 32));                            \
            FB[2*j+1] = f2tf(lds32(_pb + j * 32 + 2176));                     \
        }                                                                     \
        const uint32_t _c0 = ((uint32_t)((KS) * 32) + aK) ^ swzA;             \
        const char* _pa0 = (SA) + (aInv + _c0);                               \
        const char* _pa1 = (SA) + (aInv + (_c0 ^ 16u));                       \
        _Pragma("unroll")                                                     \
        for (int i = 0; i < 4; i++){                                          \
            FA[4*i]   = f2tf(lds32(_pa0 + i * 2048));                         \
            FA[4*i+1] = f2tf(lds32(_pa0 + i * 2048 + 1024));                  \
            FA[4*i+2] = f2tf(lds32(_pa1 + i * 2048));                         \
            FA[4*i+3] = f2tf(lds32(_pa1 + i * 2048 + 1024));                  \
        }                                                                     \
    } while (0)

#define MMA_BLOCK(FA, FB)                                                     \
    do {                                                                      \
        _Pragma("unroll")                                                     \
        for (int i = 0; i < 4; i++)                                           \
            _Pragma("unroll")                                                 \
            for (int j = 0; j < 8; j++)                                       \
                mma_tf32(acc[i][j], FA[4*i], FA[4*i+1], FA[4*i+2], FA[4*i+3], \
                         FB[2*j], FB[2*j+1]);                                 \
    } while (0)

    // ---- prologue: issue chunks 0..2, preload chunk 0 ks0 frags ----
    ISSUE(0, 0);
    asm volatile("cp.async.commit_group;" ::: "memory");
    ISSUE(32, 1);
    asm volatile("cp.async.commit_group;" ::: "memory");
    ISSUE(64, 2);
    asm volatile("cp.async.commit_group;" ::: "memory");
    asm volatile("cp.async.wait_group 1;" ::: "memory");   // stages 0,1 ready
    __syncthreads();
    LOAD_FRAGS(fa0, fb0, dsm, dsm + B_REG, 0);

    // ---- main loop: 32 chunks of BK=32, ROLLED (one body live at a time) ----
    #pragma unroll 1
    for (int c = 0; c < 32; c++){
        const int s = c & 3;
        const char* sA = dsm + s * A_STAGE;
        const char* sB = dsm + B_REG + s * B_STAGE;

        LOAD_FRAGS(fa1, fb1, sA, sB, 1);
        MMA_BLOCK(fa0, fb0);
        LOAD_FRAGS(fa0, fb0, sA, sB, 2);
        MMA_BLOCK(fa1, fb1);
        LOAD_FRAGS(fa1, fb1, sA, sB, 3);
        MMA_BLOCK(fa0, fb0);

        // mid-chunk: stage c+1 guaranteed resident, recycle stage (c+3)&3
        if (c + 3 < 32){
            asm volatile("cp.async.wait_group 1;" ::: "memory");
            __syncthreads();
            ISSUE((c + 3) * 32, (c + 3) & 3);
            asm volatile("cp.async.commit_group;" ::: "memory");
        } else {
            asm volatile("cp.async.wait_group 0;" ::: "memory");
            __syncthreads();
        }

        MMA_BLOCK(fa1, fb1);

        // preload next chunk's ks0 frags (stage untouched until chunk c+2)
        if (c + 1 < 32){
            const char* nA = dsm + ((c + 1) & 3) * A_STAGE;
            const char* nB = dsm + B_REG + ((c + 1) & 3) * B_STAGE;
            LOAD_FRAGS(fa0, fb0, nA, nB, 0);
        }
    }

    // ---- epilogue: acc + bias -> y ----
    float bias0[8], bias1[8];
    #pragma unroll
    for (int j = 0; j < 8; j++){
        const int gn = n0 + wn + j * 8 + la3 * 2;
        bias0[j] = __ldg(bc + gn);
        bias1[j] = __ldg(bc + gn + 1);
    }
    #pragma unroll
    for (int i = 0; i < 4; i++){
        const int gm = m0 + wm + i * 16 + lg;
        #pragma unroll
        for (int j = 0; j < 8; j++){
            const int gn = n0 + wn + j * 8 + la3 * 2;
            float2 v0 = make_float2(acc[i][j][0] + bias0[j], acc[i][j][1] + bias1[j]);
            float2 v1 = make_float2(acc[i][j][2] + bias0[j], acc[i][j][3] + bias1[j]);
            *(float2*)(yb + (size_t)gm * ODIM + gn)       = v0;
            *(float2*)(yb + (size_t)(gm + 8) * ODIM + gn) = v1;
        }
    }
}

extern "C" void kernel_launch(void* const* d_in, const int* in_sizes, int n_in,
                              void* d_out, int out_size)
{
    const float* x       = (const float*)d_in[0];
    const int*   cat_ids = (const int*)  d_in[1];
    const float* W       = (const float*)d_in[2];
    const float* bias    = (const float*)d_in[3];
    float*       y       = (float*)d_out;

    cudaFuncSetAttribute(cslin_mma9_kernel,
                         cudaFuncAttributeMaxDynamicSharedMemorySize, SMEM_DYN);
    dim3 grid(1024 / 128, 512 / 256, 64);   // (8, 2, 64)
    cslin_mma9_kernel<<<grid, 256, SMEM_DYN>>>(x, cat_ids, W, bias, y);
}